// round 6
// baseline (speedup 1.0000x reference)
#include <cuda_runtime.h>
#include <cuda_bf16.h>
#include <cstdint>

#define BATCH 1024
#define NF    256
#define NC    100000
#define EPSV  1e-12f
#define MOM   0.5f
#define SCLR  30.0f

// out layout: predicts [BATCH*NC] | targets [BATCH] | new_weight [NC*NF]
#define TGT_OFF  ((size_t)BATCH * (size_t)NC)
#define WOUT_OFF (TGT_OFF + (size_t)BATCH)

__device__ float g_nx[BATCH];

__device__ __forceinline__ uint32_t f2tf(float f) {
    uint32_t r; asm("cvt.rna.tf32.f32 %0, %1;" : "=r"(r) : "f"(f)); return r;
}

__device__ __forceinline__ void mma_tf32(float* c, const uint32_t* a, uint32_t b0, uint32_t b1) {
    asm volatile(
        "mma.sync.aligned.m16n8k8.row.col.f32.tf32.tf32.f32 "
        "{%0,%1,%2,%3}, {%4,%5,%6,%7}, {%8,%9}, {%0,%1,%2,%3};"
        : "+f"(c[0]), "+f"(c[1]), "+f"(c[2]), "+f"(c[3])
        : "r"(a[0]), "r"(a[1]), "r"(a[2]), "r"(a[3]), "r"(b0), "r"(b1));
}

__device__ __forceinline__ float sum4(const float4 v) {
    return v.x*v.x + v.y*v.y + v.z*v.z + v.w*v.w;
}

// ---------------------------------------------------------------------------
// Fused GEMM: C[m,n] = dot(x[m],w[n]) * 30/(|x_m||w_n|)
//  + row norms of x and w computed in-flight from the loader stream
//  + blocks with blockIdx.x==0 copy raw weight rows to wout (hidden in k-loop)
//  + blocks with blockIdx.y==0 publish g_nx for the update kernel
// BM=128 BN=128 BK=16, 256 threads, warps 4m x 2n, warp tile 32x64.
// SMEM m-major [row][16], XOR swizzle k' = k ^ (((row>>1)&3)<<2): conflict-free.
// ---------------------------------------------------------------------------
#define BK 16

__global__ void __launch_bounds__(256, 2)
gemm_kernel(const float* __restrict__ A, const float* __restrict__ Bw,
            float* __restrict__ C, float* __restrict__ wout) {
    __shared__ uint32_t As[2][128][BK];
    __shared__ uint32_t Bs[2][128][BK];
    __shared__ float sinx[128];
    __shared__ float sinw[128];

    const int tid  = threadIdx.x;
    const int m0   = blockIdx.x * 128;
    const int n0   = blockIdx.y * 128;
    const int lane = tid & 31;
    const int wid  = tid >> 5;
    const int wm   = wid >> 1;            // 0..3
    const int wn   = wid & 1;             // 0..1
    const int g    = lane >> 2;           // 0..7
    const int tg   = lane & 3;            // 0..3
    const int rb   = wm * 32;
    const int cb   = wn * 64;

    // loader mapping: f in [0,512): row = f>>2, kq = f&3; f = tid, tid+256
    const int r0 = tid >> 2;
    const int r1 = r0 + 64;
    const int kq = tid & 3;
    const float* Ap0 = A + (size_t)(m0 + r0) * NF + kq * 4;
    const float* Ap1 = A + (size_t)(m0 + r1) * NF + kq * 4;
    const int gbr0 = n0 + r0, gbr1 = n0 + r1;
    const float* Bp0 = Bw + (size_t)gbr0 * NF + kq * 4;
    const float* Bp1 = Bw + (size_t)gbr1 * NF + kq * 4;
    const bool bv0 = gbr0 < NC, bv1 = gbr1 < NC;
    const bool do_copy = (blockIdx.x == 0);
    float* Wo0 = wout + (size_t)gbr0 * NF + kq * 4;
    float* Wo1 = wout + (size_t)gbr1 * NF + kq * 4;
    // swizzled store columns (float index of first of 4)
    const int sc0 = ((kq ^ ((r0 >> 1) & 3)) << 2);
    const int sc1 = ((kq ^ ((r1 >> 1) & 3)) << 2);

    float acc[2][8][4];
    #pragma unroll
    for (int mf = 0; mf < 2; mf++)
        #pragma unroll
        for (int nf = 0; nf < 8; nf++)
            #pragma unroll
            for (int q = 0; q < 4; q++) acc[mf][nf][q] = 0.0f;

    float ssA0 = 0.f, ssA1 = 0.f, ssB0 = 0.f, ssB1 = 0.f;

    // prologue: stage 0
    {
        float4 a0 = *(const float4*)Ap0;
        float4 a1 = *(const float4*)Ap1;
        float4 b0 = bv0 ? *(const float4*)Bp0 : make_float4(0.f,0.f,0.f,0.f);
        float4 b1 = bv1 ? *(const float4*)Bp1 : make_float4(0.f,0.f,0.f,0.f);
        ssA0 += sum4(a0); ssA1 += sum4(a1);
        ssB0 += sum4(b0); ssB1 += sum4(b1);
        if (do_copy) {
            if (bv0) *(float4*)Wo0 = b0;
            if (bv1) *(float4*)Wo1 = b1;
        }
        *(uint4*)&As[0][r0][sc0] = make_uint4(f2tf(a0.x), f2tf(a0.y), f2tf(a0.z), f2tf(a0.w));
        *(uint4*)&As[0][r1][sc1] = make_uint4(f2tf(a1.x), f2tf(a1.y), f2tf(a1.z), f2tf(a1.w));
        *(uint4*)&Bs[0][r0][sc0] = make_uint4(f2tf(b0.x), f2tf(b0.y), f2tf(b0.z), f2tf(b0.w));
        *(uint4*)&Bs[0][r1][sc1] = make_uint4(f2tf(b1.x), f2tf(b1.y), f2tf(b1.z), f2tf(b1.w));
    }
    __syncthreads();

    const int swz = ((g >> 1) & 3) << 2;   // XOR for fragment k-index
    int cur = 0;

    #pragma unroll 1
    for (int kt = 0; kt < NF / BK; kt++) {
        float4 a0n, a1n, b0n, b1n;
        const bool more = (kt + 1 < NF / BK);
        if (more) {
            int ko = (kt + 1) * BK;
            a0n = *(const float4*)(Ap0 + ko);
            a1n = *(const float4*)(Ap1 + ko);
            b0n = bv0 ? *(const float4*)(Bp0 + ko) : make_float4(0.f,0.f,0.f,0.f);
            b1n = bv1 ? *(const float4*)(Bp1 + ko) : make_float4(0.f,0.f,0.f,0.f);
            ssA0 += sum4(a0n); ssA1 += sum4(a1n);
            ssB0 += sum4(b0n); ssB1 += sum4(b1n);
            if (do_copy) {
                if (bv0) *(float4*)(Wo0 + ko) = b0n;
                if (bv1) *(float4*)(Wo1 + ko) = b1n;
            }
        }
        #pragma unroll
        for (int s = 0; s < 2; s++) {
            const int k0 = (8 * s + tg)     ^ swz;
            const int k1 = (8 * s + tg + 4) ^ swz;
            uint32_t af[2][4];
            #pragma unroll
            for (int mf = 0; mf < 2; mf++) {
                int r = rb + mf * 16 + g;
                af[mf][0] = As[cur][r    ][k0];
                af[mf][1] = As[cur][r + 8][k0];
                af[mf][2] = As[cur][r    ][k1];
                af[mf][3] = As[cur][r + 8][k1];
            }
            #pragma unroll
            for (int nf = 0; nf < 8; nf++) {
                int n = cb + nf * 8 + g;
                uint32_t bf0 = Bs[cur][n][k0];
                uint32_t bf1 = Bs[cur][n][k1];
                mma_tf32(acc[0][nf], af[0], bf0, bf1);
                mma_tf32(acc[1][nf], af[1], bf0, bf1);
            }
        }
        if (more) {
            int nxt = cur ^ 1;
            *(uint4*)&As[nxt][r0][sc0] = make_uint4(f2tf(a0n.x), f2tf(a0n.y), f2tf(a0n.z), f2tf(a0n.w));
            *(uint4*)&As[nxt][r1][sc1] = make_uint4(f2tf(a1n.x), f2tf(a1n.y), f2tf(a1n.z), f2tf(a1n.w));
            *(uint4*)&Bs[nxt][r0][sc0] = make_uint4(f2tf(b0n.x), f2tf(b0n.y), f2tf(b0n.z), f2tf(b0n.w));
            *(uint4*)&Bs[nxt][r1][sc1] = make_uint4(f2tf(b1n.x), f2tf(b1n.y), f2tf(b1n.z), f2tf(b1n.w));
            __syncthreads();
            cur = nxt;
        }
    }

    // reduce row-norm partials across the 4 kq-threads of each row (quad shuffle)
    ssA0 += __shfl_xor_sync(0xffffffffu, ssA0, 1);
    ssA0 += __shfl_xor_sync(0xffffffffu, ssA0, 2);
    ssA1 += __shfl_xor_sync(0xffffffffu, ssA1, 1);
    ssA1 += __shfl_xor_sync(0xffffffffu, ssA1, 2);
    ssB0 += __shfl_xor_sync(0xffffffffu, ssB0, 1);
    ssB0 += __shfl_xor_sync(0xffffffffu, ssB0, 2);
    ssB1 += __shfl_xor_sync(0xffffffffu, ssB1, 1);
    ssB1 += __shfl_xor_sync(0xffffffffu, ssB1, 2);
    if (kq == 0) {
        float nA0 = sqrtf(ssA0), nA1 = sqrtf(ssA1);
        sinx[r0] = SCLR / fmaxf(nA0, EPSV);
        sinx[r1] = SCLR / fmaxf(nA1, EPSV);
        sinw[r0] = bv0 ? (1.0f / fmaxf(sqrtf(ssB0), EPSV)) : 0.0f;
        sinw[r1] = bv1 ? (1.0f / fmaxf(sqrtf(ssB1), EPSV)) : 0.0f;
        if (blockIdx.y == 0) {
            g_nx[m0 + r0] = nA0;
            g_nx[m0 + r1] = nA1;
        }
    }
    __syncthreads();

    // epilogue: scale + direct float2 stores
    #pragma unroll
    for (int mf = 0; mf < 2; mf++) {
        int rr = rb + mf * 16 + g;
        float sxa = sinx[rr];
        float sxb = sinx[rr + 8];
        float* rowa = C + (size_t)(m0 + rr    ) * NC;
        float* rowb = C + (size_t)(m0 + rr + 8) * NC;
        #pragma unroll
        for (int nf = 0; nf < 8; nf++) {
            int cc = cb + nf * 8 + 2 * tg;
            int n  = n0 + cc;
            if (n < NC) {
                float sw0 = sinw[cc], sw1 = sinw[cc + 1];
                float2 va = make_float2(acc[mf][nf][0] * sxa * sw0,
                                        acc[mf][nf][1] * sxa * sw1);
                float2 vb = make_float2(acc[mf][nf][2] * sxb * sw0,
                                        acc[mf][nf][3] * sxb * sw1);
                *(float2*)(rowa + n) = va;
                *(float2*)(rowb + n) = vb;
            }
        }
    }
}

// ---------------------------------------------------------------------------
// Sequential momentum update over occurrence chains + targets-as-float fold.
// Runs after gemm (needs g_nx and the wout copy).
// ---------------------------------------------------------------------------
__global__ void update_kernel(const float* __restrict__ x,
                              const int* __restrict__ tg,
                              float* __restrict__ wout,
                              float* __restrict__ tgt_out) {
    __shared__ int st[BATCH];
    __shared__ float sred[2];
    const int t = threadIdx.x;
    for (int j = t; j < BATCH; j += 64) st[j] = tg[j];
    __syncthreads();
    const int i = blockIdx.x;
    const int y = st[i];
    if (t == 0) tgt_out[i] = (float)y;
    for (int j = 0; j < i; j++)
        if (st[j] == y) return;
    float4 r = *(float4*)(wout + (size_t)y * NF + t * 4);
    for (int j = i; j < BATCH; j++) {
        if (st[j] != y) continue;
        float invn = 1.0f / fmaxf(g_nx[j], EPSV);
        float4 xv = *(const float4*)(x + (size_t)j * NF + t * 4);
        r.x = MOM * r.x + (1.0f - MOM) * xv.x * invn;
        r.y = MOM * r.y + (1.0f - MOM) * xv.y * invn;
        r.z = MOM * r.z + (1.0f - MOM) * xv.z * invn;
        r.w = MOM * r.w + (1.0f - MOM) * xv.w * invn;
        float ss = r.x*r.x + r.y*r.y + r.z*r.z + r.w*r.w;
        #pragma unroll
        for (int o = 16; o; o >>= 1) ss += __shfl_xor_sync(0xffffffffu, ss, o);
        if ((t & 31) == 0) sred[t >> 5] = ss;
        __syncthreads();
        float inv = 1.0f / fmaxf(sqrtf(sred[0] + sred[1]), EPSV);
        __syncthreads();
        r.x *= inv; r.y *= inv; r.z *= inv; r.w *= inv;
    }
    *(float4*)(wout + (size_t)y * NF + t * 4) = r;
}

// ---------------------------------------------------------------------------
extern "C" void kernel_launch(void* const* d_in, const int* in_sizes, int n_in,
                              void* d_out, int out_size) {
    const float* inputs  = (const float*)d_in[0];
    const int*   targets = (const int*)d_in[1];
    const float* weight  = (const float*)d_in[2];
    float* out = (float*)d_out;

    gemm_kernel<<<dim3(8, (NC + 127) / 128), 256>>>(inputs, weight, out, out + WOUT_OFF);
    update_kernel<<<BATCH, 64>>>(inputs, targets, out + WOUT_OFF, out + TGT_OFF);
}

// round 11
// speedup vs baseline: 1.0477x; 1.0477x over previous
#include <cuda_runtime.h>
#include <cuda_bf16.h>
#include <cstdint>

#define BATCH 1024
#define NF    256
#define NC    100000
#define EPSV  1e-12f
#define MOM   0.5f
#define SCLR  30.0f

// out layout: predicts [BATCH*NC] | targets [BATCH] | new_weight [NC*NF]
#define TGT_OFF  ((size_t)BATCH * (size_t)NC)
#define WOUT_OFF (TGT_OFF + (size_t)BATCH)

__device__ float g_nx[BATCH];

__device__ __forceinline__ uint32_t f2tf(float f) {
    uint32_t r; asm("cvt.rna.tf32.f32 %0, %1;" : "=r"(r) : "f"(f)); return r;
}

__device__ __forceinline__ void mma_tf32(float* c, const uint32_t* a, uint32_t b0, uint32_t b1) {
    asm volatile(
        "mma.sync.aligned.m16n8k8.row.col.f32.tf32.tf32.f32 "
        "{%0,%1,%2,%3}, {%4,%5,%6,%7}, {%8,%9}, {%0,%1,%2,%3};"
        : "+f"(c[0]), "+f"(c[1]), "+f"(c[2]), "+f"(c[3])
        : "r"(a[0]), "r"(a[1]), "r"(a[2]), "r"(a[3]), "r"(b0), "r"(b1));
}

__device__ __forceinline__ float sum4(const float4 v) {
    return v.x*v.x + v.y*v.y + v.z*v.z + v.w*v.w;
}

// ---------------------------------------------------------------------------
// Fused GEMM: C[m,n] = dot(x[m],w[n]) * 30/(|x_m||w_n|)
//  + row norms of x and w computed in-flight from the loader stream
//  + blocks with blockIdx.y==0 publish g_nx for the update kernel
// BM=128 BN=128 BK=16, 256 threads, warps 4m x 2n, warp tile 32x64.
// SMEM m-major [row][16], XOR swizzle k' = k ^ (((row>>1)&3)<<2): conflict-free.
// ---------------------------------------------------------------------------
#define BK 16

__global__ void __launch_bounds__(256, 2)
gemm_kernel(const float* __restrict__ A, const float* __restrict__ Bw,
            float* __restrict__ C) {
    __shared__ uint32_t As[2][128][BK];
    __shared__ uint32_t Bs[2][128][BK];
    __shared__ float sinx[128];
    __shared__ float sinw[128];

    const int tid  = threadIdx.x;
    const int m0   = blockIdx.x * 128;
    const int n0   = blockIdx.y * 128;
    const int lane = tid & 31;
    const int wid  = tid >> 5;
    const int wm   = wid >> 1;            // 0..3
    const int wn   = wid & 1;             // 0..1
    const int g    = lane >> 2;           // 0..7
    const int tg   = lane & 3;            // 0..3
    const int rb   = wm * 32;
    const int cb   = wn * 64;

    // loader mapping: f in [0,512): row = f>>2, kq = f&3; f = tid, tid+256
    const int r0 = tid >> 2;
    const int r1 = r0 + 64;
    const int kq = tid & 3;
    const float* Ap0 = A + (size_t)(m0 + r0) * NF + kq * 4;
    const float* Ap1 = A + (size_t)(m0 + r1) * NF + kq * 4;
    const int gbr0 = n0 + r0, gbr1 = n0 + r1;
    const float* Bp0 = Bw + (size_t)gbr0 * NF + kq * 4;
    const float* Bp1 = Bw + (size_t)gbr1 * NF + kq * 4;
    const bool bv0 = gbr0 < NC, bv1 = gbr1 < NC;
    // swizzled store columns (float index of first of 4)
    const int sc0 = ((kq ^ ((r0 >> 1) & 3)) << 2);
    const int sc1 = ((kq ^ ((r1 >> 1) & 3)) << 2);

    float acc[2][8][4];
    #pragma unroll
    for (int mf = 0; mf < 2; mf++)
        #pragma unroll
        for (int nf = 0; nf < 8; nf++)
            #pragma unroll
            for (int q = 0; q < 4; q++) acc[mf][nf][q] = 0.0f;

    float ssA0 = 0.f, ssA1 = 0.f, ssB0 = 0.f, ssB1 = 0.f;

    // prologue: stage 0
    {
        float4 a0 = *(const float4*)Ap0;
        float4 a1 = *(const float4*)Ap1;
        float4 b0 = bv0 ? *(const float4*)Bp0 : make_float4(0.f,0.f,0.f,0.f);
        float4 b1 = bv1 ? *(const float4*)Bp1 : make_float4(0.f,0.f,0.f,0.f);
        ssA0 += sum4(a0); ssA1 += sum4(a1);
        ssB0 += sum4(b0); ssB1 += sum4(b1);
        *(uint4*)&As[0][r0][sc0] = make_uint4(f2tf(a0.x), f2tf(a0.y), f2tf(a0.z), f2tf(a0.w));
        *(uint4*)&As[0][r1][sc1] = make_uint4(f2tf(a1.x), f2tf(a1.y), f2tf(a1.z), f2tf(a1.w));
        *(uint4*)&Bs[0][r0][sc0] = make_uint4(f2tf(b0.x), f2tf(b0.y), f2tf(b0.z), f2tf(b0.w));
        *(uint4*)&Bs[0][r1][sc1] = make_uint4(f2tf(b1.x), f2tf(b1.y), f2tf(b1.z), f2tf(b1.w));
    }
    __syncthreads();

    const int swz = ((g >> 1) & 3) << 2;   // XOR for fragment k-index
    int cur = 0;

    #pragma unroll 1
    for (int kt = 0; kt < NF / BK; kt++) {
        float4 a0n, a1n, b0n, b1n;
        const bool more = (kt + 1 < NF / BK);
        if (more) {
            int ko = (kt + 1) * BK;
            a0n = *(const float4*)(Ap0 + ko);
            a1n = *(const float4*)(Ap1 + ko);
            b0n = bv0 ? *(const float4*)(Bp0 + ko) : make_float4(0.f,0.f,0.f,0.f);
            b1n = bv1 ? *(const float4*)(Bp1 + ko) : make_float4(0.f,0.f,0.f,0.f);
            ssA0 += sum4(a0n); ssA1 += sum4(a1n);
            ssB0 += sum4(b0n); ssB1 += sum4(b1n);
        }
        #pragma unroll
        for (int s = 0; s < 2; s++) {
            const int k0 = (8 * s + tg)     ^ swz;
            const int k1 = (8 * s + tg + 4) ^ swz;
            uint32_t af[2][4];
            #pragma unroll
            for (int mf = 0; mf < 2; mf++) {
                int r = rb + mf * 16 + g;
                af[mf][0] = As[cur][r    ][k0];
                af[mf][1] = As[cur][r + 8][k0];
                af[mf][2] = As[cur][r    ][k1];
                af[mf][3] = As[cur][r + 8][k1];
            }
            #pragma unroll
            for (int nf = 0; nf < 8; nf++) {
                int n = cb + nf * 8 + g;
                uint32_t bf0 = Bs[cur][n][k0];
                uint32_t bf1 = Bs[cur][n][k1];
                mma_tf32(acc[0][nf], af[0], bf0, bf1);
                mma_tf32(acc[1][nf], af[1], bf0, bf1);
            }
        }
        if (more) {
            int nxt = cur ^ 1;
            *(uint4*)&As[nxt][r0][sc0] = make_uint4(f2tf(a0n.x), f2tf(a0n.y), f2tf(a0n.z), f2tf(a0n.w));
            *(uint4*)&As[nxt][r1][sc1] = make_uint4(f2tf(a1n.x), f2tf(a1n.y), f2tf(a1n.z), f2tf(a1n.w));
            *(uint4*)&Bs[nxt][r0][sc0] = make_uint4(f2tf(b0n.x), f2tf(b0n.y), f2tf(b0n.z), f2tf(b0n.w));
            *(uint4*)&Bs[nxt][r1][sc1] = make_uint4(f2tf(b1n.x), f2tf(b1n.y), f2tf(b1n.z), f2tf(b1n.w));
            __syncthreads();
            cur = nxt;
        }
    }

    // reduce row-norm partials across the 4 kq-threads of each row (quad shuffle)
    ssA0 += __shfl_xor_sync(0xffffffffu, ssA0, 1);
    ssA0 += __shfl_xor_sync(0xffffffffu, ssA0, 2);
    ssA1 += __shfl_xor_sync(0xffffffffu, ssA1, 1);
    ssA1 += __shfl_xor_sync(0xffffffffu, ssA1, 2);
    ssB0 += __shfl_xor_sync(0xffffffffu, ssB0, 1);
    ssB0 += __shfl_xor_sync(0xffffffffu, ssB0, 2);
    ssB1 += __shfl_xor_sync(0xffffffffu, ssB1, 1);
    ssB1 += __shfl_xor_sync(0xffffffffu, ssB1, 2);
    if (kq == 0) {
        float nA0 = sqrtf(ssA0), nA1 = sqrtf(ssA1);
        sinx[r0] = SCLR / fmaxf(nA0, EPSV);
        sinx[r1] = SCLR / fmaxf(nA1, EPSV);
        sinw[r0] = bv0 ? (1.0f / fmaxf(sqrtf(ssB0), EPSV)) : 0.0f;
        sinw[r1] = bv1 ? (1.0f / fmaxf(sqrtf(ssB1), EPSV)) : 0.0f;
        if (blockIdx.y == 0) {
            g_nx[m0 + r0] = nA0;
            g_nx[m0 + r1] = nA1;
        }
    }
    __syncthreads();

    // epilogue: scale + direct float2 stores
    #pragma unroll
    for (int mf = 0; mf < 2; mf++) {
        int rr = rb + mf * 16 + g;
        float sxa = sinx[rr];
        float sxb = sinx[rr + 8];
        float* rowa = C + (size_t)(m0 + rr    ) * NC;
        float* rowb = C + (size_t)(m0 + rr + 8) * NC;
        #pragma unroll
        for (int nf = 0; nf < 8; nf++) {
            int cc = cb + nf * 8 + 2 * tg;
            int n  = n0 + cc;
            if (n < NC) {
                float sw0 = sinw[cc], sw1 = sinw[cc + 1];
                float2 va = make_float2(acc[mf][nf][0] * sxa * sw0,
                                        acc[mf][nf][1] * sxa * sw1);
                float2 vb = make_float2(acc[mf][nf][2] * sxb * sw0,
                                        acc[mf][nf][3] * sxb * sw1);
                *(float2*)(rowa + n) = va;
                *(float2*)(rowb + n) = vb;
            }
        }
    }
}

// ---------------------------------------------------------------------------
// Plain streaming copy weight -> wout. 12500 x 512, one float4 per thread.
// ---------------------------------------------------------------------------
__global__ void __launch_bounds__(512) copy_w_kernel(const float4* __restrict__ src,
                                                     float4* __restrict__ dst) {
    size_t i = (size_t)blockIdx.x * 512 + threadIdx.x;   // < NC*NF/4 = 6,400,000
    dst[i] = src[i];
}

// ---------------------------------------------------------------------------
// Sequential momentum update over occurrence chains; parallel scans.
// Reads ORIGINAL weight row (copy kernel already populated wout; we overwrite).
// ---------------------------------------------------------------------------
__global__ void __launch_bounds__(64) update_kernel(const float* __restrict__ x,
                                                    const int* __restrict__ tg,
                                                    const float* __restrict__ w,
                                                    float* __restrict__ wout,
                                                    float* __restrict__ tgt_out) {
    __shared__ int st[BATCH];
    __shared__ uint32_t mask[BATCH / 32];
    __shared__ float sred[2];
    const int t = threadIdx.x;   // 0..63
    const int i = blockIdx.x;
    #pragma unroll
    for (int j = t; j < BATCH; j += 64) st[j] = tg[j];
    if (t < BATCH / 32) mask[t] = 0u;
    __syncthreads();
    const int y = st[i];
    if (t == 0) tgt_out[i] = (float)y;

    // parallel first-occurrence check over [0, i)
    bool dup = false;
    for (int j = t; j < i; j += 64) dup |= (st[j] == y);
    if (__syncthreads_or(dup)) return;   // uniform exit

    // build occurrence bitmask over [i, BATCH)
    for (int j = i + t; j < BATCH; j += 64)
        if (st[j] == y) atomicOr(&mask[j >> 5], 1u << (j & 31));
    __syncthreads();

    float4 r = *(const float4*)(w + (size_t)y * NF + t * 4);

    for (int wd = i >> 5; wd < BATCH / 32; wd++) {
        uint32_t m = mask[wd];           // uniform across block
        while (m) {
            int b = __ffs(m) - 1;
            m &= m - 1;
            int j = wd * 32 + b;
            float invn = 1.0f / fmaxf(g_nx[j], EPSV);
            float4 xv = *(const float4*)(x + (size_t)j * NF + t * 4);
            r.x = MOM * r.x + (1.0f - MOM) * xv.x * invn;
            r.y = MOM * r.y + (1.0f - MOM) * xv.y * invn;
            r.z = MOM * r.z + (1.0f - MOM) * xv.z * invn;
            r.w = MOM * r.w + (1.0f - MOM) * xv.w * invn;
            float ss = r.x*r.x + r.y*r.y + r.z*r.z + r.w*r.w;
            #pragma unroll
            for (int o = 16; o; o >>= 1) ss += __shfl_xor_sync(0xffffffffu, ss, o);
            if ((t & 31) == 0) sred[t >> 5] = ss;
            __syncthreads();
            float inv = 1.0f / fmaxf(sqrtf(sred[0] + sred[1]), EPSV);
            __syncthreads();
            r.x *= inv; r.y *= inv; r.z *= inv; r.w *= inv;
        }
    }

    *(float4*)(wout + (size_t)y * NF + t * 4) = r;
}

// ---------------------------------------------------------------------------
extern "C" void kernel_launch(void* const* d_in, const int* in_sizes, int n_in,
                              void* d_out, int out_size) {
    const float* inputs  = (const float*)d_in[0];
    const int*   targets = (const int*)d_in[1];
    const float* weight  = (const float*)d_in[2];
    float* out = (float*)d_out;

    gemm_kernel<<<dim3(8, (NC + 127) / 128), 256>>>(inputs, weight, out);
    copy_w_kernel<<<(NC * NF / 4) / 512, 512>>>((const float4*)weight,
                                                (float4*)(out + WOUT_OFF));
    update_kernel<<<BATCH, 64>>>(inputs, targets, weight, out + WOUT_OFF, out + TGT_OFF);
}